// round 4
// baseline (speedup 1.0000x reference)
#include <cuda_runtime.h>
#include <cuda_bf16.h>
#include <math.h>

#define CDIM   128
#define LTOK   54
#define NTOK   8
#define LN_EPS 1e-5f
#define SAW    68        // smem row stride in bf16x2 words (136 bf16): conflict-free A frags

// ---------------- device globals (precomputed weights) ----------------
__device__ float g_Af[CDIM * 64];       // folded A matrix [k][tok*8+h], fp32
__device__ uint2 g_WcB [8 * 24 * 32];   // combined [A_fold | Wv] bf16 B-frags
__device__ uint2 g_WpB [8 * 16 * 32];   // Wp  bf16 B-frags
__device__ uint2 g_Wf1B[8 * 16 * 32];   // Wf1 bf16 B-frags
__device__ uint2 g_Wf2B[8 * 16 * 32];   // Wf2 bf16 B-frags

// ---------------- helpers ----------------
__device__ __forceinline__ unsigned bfpack(float lo, float hi) {
    __nv_bfloat162 h = __floats2bfloat162_rn(lo, hi);
    return *(unsigned*)&h;
}
__device__ __forceinline__ float2 bfunpack(unsigned u) {
    return __bfloat1622float2(*(__nv_bfloat162*)&u);
}

__device__ __forceinline__ void mma_bf16(float* c, const unsigned* a, unsigned b0, unsigned b1) {
    asm volatile(
        "mma.sync.aligned.m16n8k16.row.col.f32.bf16.bf16.f32 "
        "{%0,%1,%2,%3},{%4,%5,%6,%7},{%8,%9},{%0,%1,%2,%3};"
        : "+f"(c[0]), "+f"(c[1]), "+f"(c[2]), "+f"(c[3])
        : "r"(a[0]), "r"(a[1]), "r"(a[2]), "r"(a[3]), "r"(b0), "r"(b1));
}

__device__ __forceinline__ float warp_sum(float v) {
    v += __shfl_xor_sync(0xffffffffu, v, 16);
    v += __shfl_xor_sync(0xffffffffu, v, 8);
    v += __shfl_xor_sync(0xffffffffu, v, 4);
    v += __shfl_xor_sync(0xffffffffu, v, 2);
    v += __shfl_xor_sync(0xffffffffu, v, 1);
    return v;
}

// ---------------- P1: LN1 -> q -> A fold (single small block) ----------------
__global__ void precompute1_kernel(
    const float* __restrict__ query,
    const float* __restrict__ ln1_g, const float* __restrict__ ln1_b,
    const float* __restrict__ Wq, const float* __restrict__ bq,
    const float* __restrict__ Wk)
{
    __shared__ float s_qn[NTOK * CDIM];
    __shared__ float s_q[NTOK * CDIM];
    const int tid = threadIdx.x;   // 256
    const int warp = tid >> 5, lane = tid & 31;

    if (warp < NTOK) {
        const int r = warp;
        float4 xv = *(const float4*)&query[r * CDIM + lane * 4];
        float s1 = xv.x + xv.y + xv.z + xv.w;
        float s2 = xv.x * xv.x + xv.y * xv.y + xv.z * xv.z + xv.w * xv.w;
        s1 = warp_sum(s1);
        s2 = warp_sum(s2);
        float m = s1 * (1.0f / 128.0f);
        float var = s2 * (1.0f / 128.0f) - m * m;
        float rs = rsqrtf(var + LN_EPS);
        float4 g = *(const float4*)&ln1_g[lane * 4];
        float4 be = *(const float4*)&ln1_b[lane * 4];
        float4 o;
        o.x = (xv.x - m) * rs * g.x + be.x;
        o.y = (xv.y - m) * rs * g.y + be.y;
        o.z = (xv.z - m) * rs * g.z + be.z;
        o.w = (xv.w - m) * rs * g.w + be.w;
        *(float4*)&s_qn[r * CDIM + lane * 4] = o;
    }
    __syncthreads();

    for (int idx = tid; idx < NTOK * CDIM; idx += 256) {
        int t = idx >> 7, o = idx & 127;
        float acc = bq[o];
        #pragma unroll 8
        for (int c = 0; c < CDIM; c++) acc += s_qn[t * CDIM + c] * Wq[c * CDIM + o];
        s_q[idx] = acc;
    }
    __syncthreads();

    // A_fold[k][tok*8+h] = 0.25 * sum_j q[tok][h*16+j] * Wk[k][h*16+j]
    // (bk contribution is constant per (tok,h) logit column -> cancels in softmax)
    for (int idx = tid; idx < CDIM * 64; idx += 256) {
        int k = idx >> 6, c = idx & 63;
        int tok = c >> 3, h = c & 7;
        float acc = 0.0f;
        #pragma unroll
        for (int j = 0; j < 16; j++)
            acc += s_q[tok * CDIM + h * 16 + j] * Wk[k * CDIM + h * 16 + j];
        g_Af[idx] = 0.25f * acc;
    }
}

// ---------------- P2: pack all weights into bf16 B-fragment order ----------------
__global__ void precompute2_kernel(
    const float* __restrict__ Wv,
    const float* __restrict__ Wp,
    const float* __restrict__ Wf1,
    const float* __restrict__ Wf2)
{
    const int gid = blockIdx.x * blockDim.x + threadIdx.x;
    if (gid < 6144) {
        const int lane = gid & 31;
        const int rest = gid >> 5;
        const int nt = rest % 24;
        const int ks = rest / 24;
        const int g = lane >> 2, t = lane & 3;
        const int c = nt * 8 + g;
        const int k0 = ks * 16 + 2 * t;
        float f0, f1, f2, f3;
        if (c < 64) {
            f0 = g_Af[(k0    ) * 64 + c];
            f1 = g_Af[(k0 + 1) * 64 + c];
            f2 = g_Af[(k0 + 8) * 64 + c];
            f3 = g_Af[(k0 + 9) * 64 + c];
        } else {
            const int cc = c - 64;
            f0 = Wv[(k0    ) * CDIM + cc];
            f1 = Wv[(k0 + 1) * CDIM + cc];
            f2 = Wv[(k0 + 8) * CDIM + cc];
            f3 = Wv[(k0 + 9) * CDIM + cc];
        }
        g_WcB[gid] = make_uint2(bfpack(f0, f1), bfpack(f2, f3));
    } else if (gid < 18432) {
        const int r = (gid - 6144) & 4095;
        const int m = (gid - 6144) >> 12;
        const int lane = r & 31;
        const int rest = r >> 5;
        const int nt = rest & 15;
        const int ks = rest >> 4;
        const int g = lane >> 2, t = lane & 3;
        const int c = nt * 8 + g;
        const int k0 = ks * 16 + 2 * t;
        const float* W = (m == 0) ? Wp : (m == 1) ? Wf1 : Wf2;
        uint2 v = make_uint2(
            bfpack(W[k0 * CDIM + c], W[(k0 + 1) * CDIM + c]),
            bfpack(W[(k0 + 8) * CDIM + c], W[(k0 + 9) * CDIM + c]));
        if (m == 0)      g_WpB [r] = v;
        else if (m == 1) g_Wf1B[r] = v;
        else             g_Wf2B[r] = v;
    }
}

// ---------------- megakernel: 1 batch per block, 512 threads, occ 2 ----------------
// smem layout (4B words):
//   sA  [64][SAW]  bf16x2 : tgt, then V after GEMM1           4352 w
//   sD  [54][68]   fp32   : dots                              3672 w
//   sAt [16][SAW]  bf16x2 : attn out / LN2 out (rows 8-15=0)  1088 w
//   sF  [16][SAW]  bf16x2 : gelu out (rows 8-15=0)            1088 w
//   sX  [8][128]   fp32   : residual x                        1024 w
#define W_A   (64 * SAW)
#define W_D   (54 * 68)
#define W_AT  (16 * SAW)
#define W_F   (16 * SAW)
#define W_X   (8 * 128)
#define SM_MEGA_BYTES ((W_A + W_D + W_AT + W_F + W_X) * 4)

__global__ __launch_bounds__(512, 2) void mega_kernel(
    const float* __restrict__ tgt,
    const float* __restrict__ query,
    const float* __restrict__ bv,
    const float* __restrict__ bp,
    const float* __restrict__ ln2_g, const float* __restrict__ ln2_b,
    const float* __restrict__ bf1, const float* __restrict__ bf2,
    float* __restrict__ out)
{
    extern __shared__ unsigned smw[];
    unsigned* sA  = smw;
    float*    sD  = (float*)(smw + W_A);
    unsigned* sAt = smw + W_A + W_D;
    unsigned* sF  = smw + W_A + W_D + W_AT;
    float*    sX  = (float*)(smw + W_A + W_D + W_AT + W_F);

    const int tid = threadIdx.x;
    const int w = tid >> 5, lane = tid & 31;
    const int g = lane >> 2, t = lane & 3;
    const int b = blockIdx.x;

    // ---- Phase 0: stage tgt (54 rows) as bf16; zero pad rows of sAt/sF ----
    {
        const float4* gt = (const float4*)(tgt + (size_t)b * (LTOK * CDIM));
        for (int i = tid; i < LTOK * 32; i += 512) {
            const int row = i >> 5, c4 = i & 31;
            float4 v = __ldg(gt + i);
            *(uint2*)&sA[row * SAW + c4 * 2] = make_uint2(bfpack(v.x, v.y), bfpack(v.z, v.w));
        }
        // zero sAt rows 8-15 and sF rows 8-15 (upper half of M=16 mma tiles)
        for (int i = tid; i < 8 * SAW; i += 512) {
            sAt[8 * SAW + i] = 0u;
            sF [8 * SAW + i] = 0u;
        }
    }
    __syncthreads();

    // ---- Phase 1: GEMM1 [64(54),128] @ [128,192] -> dots(64 cols) | V(128 cols) ----
    {
        const int mg = w >> 3;        // 2 m-tile group (tiles 2mg, 2mg+1)
        const int ng = w & 7;         // 3 n-tiles each
        float C[2][3][4];
        #pragma unroll
        for (int m = 0; m < 2; m++)
            #pragma unroll
            for (int n = 0; n < 3; n++)
                #pragma unroll
                for (int q = 0; q < 4; q++) C[m][n][q] = 0.0f;

        #pragma unroll 1
        for (int ks = 0; ks < 8; ks++) {
            uint2 B[3];
            #pragma unroll
            for (int n = 0; n < 3; n++)
                B[n] = __ldg(&g_WcB[(ks * 24 + ng * 3 + n) * 32 + lane]);
            #pragma unroll
            for (int m = 0; m < 2; m++) {
                const unsigned* pa = sA + ((mg * 2 + m) * 16 + g) * SAW + ks * 8 + t;
                unsigned A4[4];
                A4[0] = pa[0];
                A4[1] = pa[8 * SAW];
                A4[2] = pa[4];
                A4[3] = pa[8 * SAW + 4];
                #pragma unroll
                for (int n = 0; n < 3; n++)
                    mma_bf16(C[m][n], A4, B[n].x, B[n].y);
            }
        }
        __syncthreads();   // all A reads complete before V overwrites sA

        #pragma unroll
        for (int m = 0; m < 2; m++) {
            const int r1 = (mg * 2 + m) * 16 + g;
            #pragma unroll
            for (int n = 0; n < 3; n++) {
                const int nt = ng * 3 + n;
                if (nt < 8) {
                    const int c0 = nt * 8 + 2 * t;
                    float* d0 = sD + r1 * 68 + c0;
                    if (r1 < LTOK)     *(float2*)d0            = make_float2(C[m][n][0], C[m][n][1]);
                    if (r1 + 8 < LTOK) *(float2*)(d0 + 8 * 68) = make_float2(C[m][n][2], C[m][n][3]);
                } else {
                    const int wrd = (nt - 8) * 4 + t;   // bf16x2 word within V row
                    unsigned* v0 = sA + r1 * SAW + wrd;
                    if (r1 < LTOK)     v0[0]       = bfpack(C[m][n][0], C[m][n][1]);
                    if (r1 + 8 < LTOK) v0[8 * SAW] = bfpack(C[m][n][2], C[m][n][3]);
                }
            }
        }
    }
    __syncthreads();

    // ---- Phase 2: softmax + AV: 128 threads, task = (tok,head) x half-V ----
    if (tid < 128) {
        const int th = tid >> 1, half = tid & 1;
        const int tok = th >> 3, h = th & 7;
        const int ridx = (tok < 2) ? tok : (tok - 2);
        const int hb = ridx / 3, wb = ridx % 3;
        const int l0 = hb * 27 + wb * 3;
        int ls[9];
        #pragma unroll
        for (int d = 0; d < 9; d++) ls[d] = l0 + (d / 3) * 9 + (d % 3);

        float dv[9];
        float mx = -1e30f;
        #pragma unroll
        for (int d = 0; d < 9; d++) {
            dv[d] = sD[ls[d] * 68 + th];
            mx = fmaxf(mx, dv[d]);
        }
        float ssum = 0.0f;
        #pragma unroll
        for (int d = 0; d < 9; d++) {
            dv[d] = __expf(dv[d] - mx);
            ssum += dv[d];
        }
        const float inv = 1.0f / ssum;
        float acc[8];
        #pragma unroll
        for (int j = 0; j < 8; j++) acc[j] = 0.0f;
        #pragma unroll
        for (int d = 0; d < 9; d++) {
            const uint4 vv = *(const uint4*)&sA[ls[d] * SAW + h * 8 + half * 4];
            float2 p;
            p = bfunpack(vv.x); acc[0] += dv[d] * p.x; acc[1] += dv[d] * p.y;
            p = bfunpack(vv.y); acc[2] += dv[d] * p.x; acc[3] += dv[d] * p.y;
            p = bfunpack(vv.z); acc[4] += dv[d] * p.x; acc[5] += dv[d] * p.y;
            p = bfunpack(vv.w); acc[6] += dv[d] * p.x; acc[7] += dv[d] * p.y;
        }
        unsigned* ao = sAt + tok * SAW + h * 8 + half * 4;
        const int cb = h * 16 + half * 8;
        #pragma unroll
        for (int j = 0; j < 4; j++) {
            float b0 = __ldg(bv + cb + 2 * j);
            float b1 = __ldg(bv + cb + 2 * j + 1);
            ao[j] = bfpack(acc[2 * j] * inv + b0, acc[2 * j + 1] * inv + b1);
        }
    }
    __syncthreads();

    // ---- Phase 3: proj: x = query + attn @ Wp + bp -> sX (fp32) ----
    {
        float Cp[4] = {0.f, 0.f, 0.f, 0.f};
        #pragma unroll 1
        for (int ks = 0; ks < 8; ks++) {
            const unsigned* pa = sAt + g * SAW + ks * 8 + t;
            unsigned A4[4];
            A4[0] = pa[0];
            A4[1] = pa[8 * SAW];   // zero rows
            A4[2] = pa[4];
            A4[3] = pa[8 * SAW + 4];
            uint2 bb = __ldg(&g_WpB[(ks * 16 + w) * 32 + lane]);
            mma_bf16(Cp, A4, bb.x, bb.y);
        }
        const int c0 = w * 8 + 2 * t;
        const float bp0 = __ldg(bp + c0), bp1 = __ldg(bp + c0 + 1);
        const float q0 = __ldg(query + g * CDIM + c0);
        const float q1 = __ldg(query + g * CDIM + c0 + 1);
        *(float2*)&sX[g * CDIM + c0] = make_float2(Cp[0] + bp0 + q0, Cp[1] + bp1 + q1);
    }
    __syncthreads();

    // ---- Phase 4: LN2 (8 rows, warp per row) -> sAt rows 0-7 (bf16) ----
    if (w < 8) {
        const int row = w;
        float4 xv = *(const float4*)&sX[row * CDIM + lane * 4];
        float s1 = xv.x + xv.y + xv.z + xv.w;
        float s2 = xv.x * xv.x + xv.y * xv.y + xv.z * xv.z + xv.w * xv.w;
        s1 = warp_sum(s1);
        s2 = warp_sum(s2);
        float m = s1 * (1.0f / 128.0f);
        float var = s2 * (1.0f / 128.0f) - m * m;
        float rs = rsqrtf(var + LN_EPS);
        float4 gv  = __ldg((const float4*)ln2_g + lane);
        float4 bv2 = __ldg((const float4*)ln2_b + lane);
        *(uint2*)&sAt[row * SAW + lane * 2] = make_uint2(
            bfpack((xv.x - m) * rs * gv.x + bv2.x, (xv.y - m) * rs * gv.y + bv2.y),
            bfpack((xv.z - m) * rs * gv.z + bv2.z, (xv.w - m) * rs * gv.w + bv2.w));
    }
    __syncthreads();

    // ---- Phase 5: f = gelu(ln @ Wf1 + bf1) -> sF rows 0-7 ----
    {
        float Cf[4] = {0.f, 0.f, 0.f, 0.f};
        #pragma unroll 1
        for (int ks = 0; ks < 8; ks++) {
            const unsigned* pa = sAt + g * SAW + ks * 8 + t;
            unsigned A4[4];
            A4[0] = pa[0];
            A4[1] = pa[8 * SAW];
            A4[2] = pa[4];
            A4[3] = pa[8 * SAW + 4];
            uint2 bb = __ldg(&g_Wf1B[(ks * 16 + w) * 32 + lane]);
            mma_bf16(Cf, A4, bb.x, bb.y);
        }
        const int c0 = w * 8 + 2 * t;
        float v0 = Cf[0] + __ldg(bf1 + c0);
        float v1 = Cf[1] + __ldg(bf1 + c0 + 1);
        v0 = 0.5f * v0 * (1.0f + erff(v0 * 0.70710678118654752f));
        v1 = 0.5f * v1 * (1.0f + erff(v1 * 0.70710678118654752f));
        sF[g * SAW + w * 4 + t] = bfpack(v0, v1);
    }
    __syncthreads();

    // ---- Phase 6: out = x + f @ Wf2 + bf2 ----
    {
        float Co[4] = {0.f, 0.f, 0.f, 0.f};
        #pragma unroll 1
        for (int ks = 0; ks < 8; ks++) {
            const unsigned* pa = sF + g * SAW + ks * 8 + t;
            unsigned A4[4];
            A4[0] = pa[0];
            A4[1] = pa[8 * SAW];
            A4[2] = pa[4];
            A4[3] = pa[8 * SAW + 4];
            uint2 bb = __ldg(&g_Wf2B[(ks * 16 + w) * 32 + lane]);
            mma_bf16(Co, A4, bb.x, bb.y);
        }
        const int c0 = w * 8 + 2 * t;
        const float b20 = __ldg(bf2 + c0), b21 = __ldg(bf2 + c0 + 1);
        const float x0 = sX[g * CDIM + c0], x1 = sX[g * CDIM + c0 + 1];
        *(float2*)&out[((size_t)b * NTOK + g) * CDIM + c0] =
            make_float2(Co[0] + b20 + x0, Co[1] + b21 + x1);
    }
}

// ---------------- launch ----------------
extern "C" void kernel_launch(void* const* d_in, const int* in_sizes, int n_in,
                              void* d_out, int out_size)
{
    const float* query = (const float*)d_in[0];
    const float* tgt   = (const float*)d_in[1];
    const float* ln1_g = (const float*)d_in[2];
    const float* ln1_b = (const float*)d_in[3];
    const float* ln2_g = (const float*)d_in[4];
    const float* ln2_b = (const float*)d_in[5];
    const float* Wq    = (const float*)d_in[6];
    const float* bq    = (const float*)d_in[7];
    const float* Wk    = (const float*)d_in[8];
    const float* Wv    = (const float*)d_in[10];
    const float* bv    = (const float*)d_in[11];
    const float* Wp    = (const float*)d_in[12];
    const float* bp    = (const float*)d_in[13];
    const float* Wf1   = (const float*)d_in[14];
    const float* bf1   = (const float*)d_in[15];
    const float* Wf2   = (const float*)d_in[16];
    const float* bf2   = (const float*)d_in[17];
    float* out = (float*)d_out;

    const int B = in_sizes[1] / (LTOK * CDIM);

    cudaFuncSetAttribute(mega_kernel, cudaFuncAttributeMaxDynamicSharedMemorySize, SM_MEGA_BYTES);

    precompute1_kernel<<<1, 256>>>(query, ln1_g, ln1_b, Wq, bq, Wk);
    precompute2_kernel<<<72, 256>>>(Wv, Wp, Wf1, Wf2);
    mega_kernel<<<B, 512, SM_MEGA_BYTES>>>(
        tgt, query, bv, bp, ln2_g, ln2_b, bf1, bf2, out);
}

// round 5
// speedup vs baseline: 1.2418x; 1.2418x over previous
#include <cuda_runtime.h>
#include <cuda_bf16.h>
#include <math.h>

#define CDIM   128
#define LTOK   54
#define NTOK   8
#define LN_EPS 1e-5f
#define SAW    68        // smem row stride in bf16x2 words (136 bf16)

// ---------------- device globals (precomputed weights) ----------------
__device__ float g_Af[CDIM * 64];       // folded A matrix [k][tok*8+h], fp32
__device__ uint2 g_WcB [8 * 24 * 32];   // combined [A_fold | Wv] bf16 B-frags
__device__ uint2 g_WpB [8 * 16 * 32];   // Wp  bf16 B-frags
__device__ uint2 g_Wf1B[8 * 16 * 32];   // Wf1 bf16 B-frags
__device__ uint2 g_Wf2B[8 * 16 * 32];   // Wf2 bf16 B-frags

// ---------------- helpers ----------------
__device__ __forceinline__ unsigned bfpack(float lo, float hi) {
    __nv_bfloat162 h = __floats2bfloat162_rn(lo, hi);
    return *(unsigned*)&h;
}
__device__ __forceinline__ float2 bfunpack(unsigned u) {
    return __bfloat1622float2(*(__nv_bfloat162*)&u);
}

__device__ __forceinline__ void mma_bf16(float* c, const unsigned* a, unsigned b0, unsigned b1) {
    asm volatile(
        "mma.sync.aligned.m16n8k16.row.col.f32.bf16.bf16.f32 "
        "{%0,%1,%2,%3},{%4,%5,%6,%7},{%8,%9},{%0,%1,%2,%3};"
        : "+f"(c[0]), "+f"(c[1]), "+f"(c[2]), "+f"(c[3])
        : "r"(a[0]), "r"(a[1]), "r"(a[2]), "r"(a[3]), "r"(b0), "r"(b1));
}

__device__ __forceinline__ float warp_sum(float v) {
    v += __shfl_xor_sync(0xffffffffu, v, 16);
    v += __shfl_xor_sync(0xffffffffu, v, 8);
    v += __shfl_xor_sync(0xffffffffu, v, 4);
    v += __shfl_xor_sync(0xffffffffu, v, 2);
    v += __shfl_xor_sync(0xffffffffu, v, 1);
    return v;
}

// ---------------- P1: LN1 -> q -> A fold (1024 threads, parallel inside) ----------------
__global__ __launch_bounds__(1024, 1) void precompute1_kernel(
    const float* __restrict__ query,
    const float* __restrict__ ln1_g, const float* __restrict__ ln1_b,
    const float* __restrict__ Wq, const float* __restrict__ bq,
    const float* __restrict__ Wk)
{
    __shared__ float s_qn[NTOK * CDIM];
    __shared__ float s_q[NTOK * CDIM];
    const int tid = threadIdx.x;
    const int warp = tid >> 5, lane = tid & 31;

    if (warp < NTOK) {
        const int r = warp;
        float4 xv = *(const float4*)&query[r * CDIM + lane * 4];
        float s1 = xv.x + xv.y + xv.z + xv.w;
        float s2 = xv.x * xv.x + xv.y * xv.y + xv.z * xv.z + xv.w * xv.w;
        s1 = warp_sum(s1);
        s2 = warp_sum(s2);
        float m = s1 * (1.0f / 128.0f);
        float var = s2 * (1.0f / 128.0f) - m * m;
        float rs = rsqrtf(var + LN_EPS);
        float4 g = *(const float4*)&ln1_g[lane * 4];
        float4 be = *(const float4*)&ln1_b[lane * 4];
        float4 o;
        o.x = (xv.x - m) * rs * g.x + be.x;
        o.y = (xv.y - m) * rs * g.y + be.y;
        o.z = (xv.z - m) * rs * g.z + be.z;
        o.w = (xv.w - m) * rs * g.w + be.w;
        *(float4*)&s_qn[r * CDIM + lane * 4] = o;
    }
    __syncthreads();

    // q = qn @ Wq + bq : one thread per output element (1024 = 8x128)
    {
        const int t = tid >> 7, o = tid & 127;
        float acc = bq[o];
        #pragma unroll 8
        for (int c = 0; c < CDIM; c++)
            acc += s_qn[t * CDIM + c] * __ldg(Wq + c * CDIM + o);
        s_q[tid] = acc;
    }
    __syncthreads();

    // A_fold[k][tok*8+h] = 0.25 * sum_j q[tok][h*16+j] * Wk[k][h*16+j]
    // (bk contribution is constant per (tok,h) logit column -> cancels in softmax)
    for (int idx = tid; idx < CDIM * 64; idx += 1024) {
        int k = idx >> 6, c = idx & 63;
        int tok = c >> 3, h = c & 7;
        float acc = 0.0f;
        #pragma unroll
        for (int j = 0; j < 16; j++)
            acc += s_q[tok * CDIM + h * 16 + j] * __ldg(Wk + k * CDIM + h * 16 + j);
        g_Af[idx] = 0.25f * acc;
    }
}

// ---------------- P2: pack all weights into bf16 B-fragment order ----------------
__global__ void precompute2_kernel(
    const float* __restrict__ Wv,
    const float* __restrict__ Wp,
    const float* __restrict__ Wf1,
    const float* __restrict__ Wf2)
{
    const int gid = blockIdx.x * blockDim.x + threadIdx.x;
    if (gid < 6144) {
        const int lane = gid & 31;
        const int rest = gid >> 5;
        const int nt = rest % 24;
        const int ks = rest / 24;
        const int g = lane >> 2, t = lane & 3;
        const int c = nt * 8 + g;
        const int k0 = ks * 16 + 2 * t;
        float f0, f1, f2, f3;
        if (c < 64) {
            f0 = g_Af[(k0    ) * 64 + c];
            f1 = g_Af[(k0 + 1) * 64 + c];
            f2 = g_Af[(k0 + 8) * 64 + c];
            f3 = g_Af[(k0 + 9) * 64 + c];
        } else {
            const int cc = c - 64;
            f0 = Wv[(k0    ) * CDIM + cc];
            f1 = Wv[(k0 + 1) * CDIM + cc];
            f2 = Wv[(k0 + 8) * CDIM + cc];
            f3 = Wv[(k0 + 9) * CDIM + cc];
        }
        g_WcB[gid] = make_uint2(bfpack(f0, f1), bfpack(f2, f3));
    } else if (gid < 18432) {
        const int r = (gid - 6144) & 4095;
        const int m = (gid - 6144) >> 12;
        const int lane = r & 31;
        const int rest = r >> 5;
        const int nt = rest & 15;
        const int ks = rest >> 4;
        const int g = lane >> 2, t = lane & 3;
        const int c = nt * 8 + g;
        const int k0 = ks * 16 + 2 * t;
        const float* W = (m == 0) ? Wp : (m == 1) ? Wf1 : Wf2;
        uint2 v = make_uint2(
            bfpack(W[k0 * CDIM + c], W[(k0 + 1) * CDIM + c]),
            bfpack(W[(k0 + 8) * CDIM + c], W[(k0 + 9) * CDIM + c]));
        if (m == 0)      g_WpB [r] = v;
        else if (m == 1) g_Wf1B[r] = v;
        else             g_Wf2B[r] = v;
    }
}

// ---------------- megakernel: 2 batches per block, 1024 threads ----------------
// smem layout (4B words):
//   sA  [128][SAW] bf16x2 : tgt (2x64 rows), then V after GEMM1   8704 w
//   sD  [108][68]  fp32   : dots; later reused as k-split scratch 7344 w
//   sAt [16][SAW]  bf16x2 : attn out / LN2 out                    1088 w
//   sF  [16][SAW]  bf16x2 : gelu out                              1088 w
//   sX  [16][128]  fp32   : residual x                            2048 w
#define W_A   (128 * SAW)
#define W_D   (108 * 68)
#define W_AT  (16 * SAW)
#define W_F   (16 * SAW)
#define W_X   (16 * 128)
#define SM_MEGA_BYTES ((W_A + W_D + W_AT + W_F + W_X) * 4)

__global__ __launch_bounds__(1024, 1) void mega_kernel(
    const float* __restrict__ tgt,
    const float* __restrict__ query,
    const float* __restrict__ bv,
    const float* __restrict__ bp,
    const float* __restrict__ ln2_g, const float* __restrict__ ln2_b,
    const float* __restrict__ bf1, const float* __restrict__ bf2,
    float* __restrict__ out)
{
    extern __shared__ unsigned smw[];
    unsigned* sA  = smw;
    float*    sD  = (float*)(smw + W_A);
    unsigned* sAt = smw + W_A + W_D;
    unsigned* sF  = smw + W_A + W_D + W_AT;
    float*    sX  = (float*)(smw + W_A + W_D + W_AT + W_F);
    float*    sScr = sD;   // k-split scratch (16 n-tiles x 32 lanes x 4 floats = 2048 f)

    const int tid = threadIdx.x;
    const int w = tid >> 5, lane = tid & 31;
    const int g = lane >> 2, t = lane & 3;
    const int b0 = blockIdx.x * 2;

    // ---- Phase 0: stage tgt (2 batches, 108 rows) as bf16 ----
    {
        const float4* gt = (const float4*)(tgt + (size_t)b0 * (LTOK * CDIM));
        for (int i = tid; i < 2 * LTOK * 32; i += 1024) {
            const int row = i >> 5, c4 = i & 31;
            float4 v = __ldg(gt + i);
            const int bb = (row >= LTOK) ? 1 : 0;
            const int r = row - bb * LTOK;
            *(uint2*)&sA[(bb * 64 + r) * SAW + c4 * 2] =
                make_uint2(bfpack(v.x, v.y), bfpack(v.z, v.w));
        }
    }
    __syncthreads();

    // ---- Phase 1: GEMM1 [128(2x54),128] @ [128,192] -> dots(64 cols) | V(128 cols) ----
    {
        const int mg = w >> 3;        // m-tile group: tiles {2mg, 2mg+1}
        const int ng = w & 7;         // 3 n-tiles each
        float C[2][3][4];
        #pragma unroll
        for (int m = 0; m < 2; m++)
            #pragma unroll
            for (int n = 0; n < 3; n++)
                #pragma unroll
                for (int q = 0; q < 4; q++) C[m][n][q] = 0.0f;

        #pragma unroll 2
        for (int ks = 0; ks < 8; ks++) {
            uint2 B[3];
            #pragma unroll
            for (int n = 0; n < 3; n++)
                B[n] = __ldg(&g_WcB[(ks * 24 + ng * 3 + n) * 32 + lane]);
            #pragma unroll
            for (int m = 0; m < 2; m++) {
                const unsigned* pa = sA + ((mg * 2 + m) * 16 + g) * SAW + ks * 8 + t;
                unsigned A4[4];
                A4[0] = pa[0];
                A4[1] = pa[8 * SAW];
                A4[2] = pa[4];
                A4[3] = pa[8 * SAW + 4];
                #pragma unroll
                for (int n = 0; n < 3; n++)
                    mma_bf16(C[m][n], A4, B[n].x, B[n].y);
            }
        }
        __syncthreads();   // all A reads complete before V overwrites sA

        #pragma unroll
        for (int m = 0; m < 2; m++) {
            const int r1 = (mg * 2 + m) * 16 + g;   // global row 0..127
            const int bb = r1 >> 6, rl = r1 & 63;
            #pragma unroll
            for (int n = 0; n < 3; n++) {
                const int nt = ng * 3 + n;
                if (nt < 8) {
                    const int c0 = nt * 8 + 2 * t;
                    float* d0 = sD + (bb * LTOK + rl) * 68 + c0;
                    if (rl < LTOK)     *(float2*)d0            = make_float2(C[m][n][0], C[m][n][1]);
                    if (rl + 8 < LTOK) *(float2*)(d0 + 8 * 68) = make_float2(C[m][n][2], C[m][n][3]);
                } else {
                    const int wrd = (nt - 8) * 4 + t;
                    unsigned* v0 = sA + r1 * SAW + wrd;
                    if (rl < LTOK)     v0[0]       = bfpack(C[m][n][0], C[m][n][1]);
                    if (rl + 8 < LTOK) v0[8 * SAW] = bfpack(C[m][n][2], C[m][n][3]);
                }
            }
        }
    }
    __syncthreads();

    // ---- Phase 2: softmax + AV: 256 tasks (2 batch x 8 tok x 8 head x 2 half) ----
    if (tid < 256) {
        const int bb = tid >> 7;
        const int rest = tid & 127;
        const int th = rest >> 1, half = rest & 1;
        const int tok = th >> 3, h = th & 7;
        const int ridx = (tok < 2) ? tok : (tok - 2);
        const int hb = ridx / 3, wb = ridx % 3;
        const int l0 = hb * 27 + wb * 3;
        int ls[9];
        #pragma unroll
        for (int d = 0; d < 9; d++) ls[d] = l0 + (d / 3) * 9 + (d % 3);

        float dv[9];
        float mx = -1e30f;
        #pragma unroll
        for (int d = 0; d < 9; d++) {
            dv[d] = sD[(bb * LTOK + ls[d]) * 68 + th];
            mx = fmaxf(mx, dv[d]);
        }
        float ssum = 0.0f;
        #pragma unroll
        for (int d = 0; d < 9; d++) {
            dv[d] = __expf(dv[d] - mx);
            ssum += dv[d];
        }
        const float inv = 1.0f / ssum;
        float acc[8];
        #pragma unroll
        for (int j = 0; j < 8; j++) acc[j] = 0.0f;
        #pragma unroll
        for (int d = 0; d < 9; d++) {
            const uint4 vv = *(const uint4*)&sA[(bb * 64 + ls[d]) * SAW + h * 8 + half * 4];
            float2 p;
            p = bfunpack(vv.x); acc[0] += dv[d] * p.x; acc[1] += dv[d] * p.y;
            p = bfunpack(vv.y); acc[2] += dv[d] * p.x; acc[3] += dv[d] * p.y;
            p = bfunpack(vv.z); acc[4] += dv[d] * p.x; acc[5] += dv[d] * p.y;
            p = bfunpack(vv.w); acc[6] += dv[d] * p.x; acc[7] += dv[d] * p.y;
        }
        unsigned* ao = sAt + (bb * 8 + tok) * SAW + h * 8 + half * 4;
        const int cb = h * 16 + half * 8;
        #pragma unroll
        for (int j = 0; j < 4; j++) {
            float v0 = __ldg(bv + cb + 2 * j);
            float v1 = __ldg(bv + cb + 2 * j + 1);
            ao[j] = bfpack(acc[2 * j] * inv + v0, acc[2 * j + 1] * inv + v1);
        }
    }
    __syncthreads();   // sD free from here: reuse as k-split scratch

    // ===== tail phases: M=16 x 128, 16 n-tiles x 2 k-halves (all 32 warps) =====
    const int nt = w & 15;
    const int kh = w >> 4;
    const int ksBeg = kh * 4, ksEnd = kh * 4 + 4;

    // ---- Phase 3: proj: x = query + attn @ Wp + bp -> sX ----
    {
        float C[4] = {0.f, 0.f, 0.f, 0.f};
        #pragma unroll
        for (int ks = ksBeg; ks < ksEnd; ks++) {
            const unsigned* pa = sAt + g * SAW + ks * 8 + t;
            unsigned A4[4];
            A4[0] = pa[0];
            A4[1] = pa[8 * SAW];
            A4[2] = pa[4];
            A4[3] = pa[8 * SAW + 4];
            uint2 bb = __ldg(&g_WpB[(ks * 16 + nt) * 32 + lane]);
            mma_bf16(C, A4, bb.x, bb.y);
        }
        if (kh == 1)
            *(float4*)&sScr[(nt * 32 + lane) * 4] = make_float4(C[0], C[1], C[2], C[3]);
        __syncthreads();
        if (kh == 0) {
            float4 p = *(const float4*)&sScr[(nt * 32 + lane) * 4];
            const int c0 = nt * 8 + 2 * t;
            const float bp0 = __ldg(bp + c0), bp1 = __ldg(bp + c0 + 1);
            const float q0 = __ldg(query + g * CDIM + c0);
            const float q1 = __ldg(query + g * CDIM + c0 + 1);
            *(float2*)&sX[g * CDIM + c0] =
                make_float2(C[0] + p.x + bp0 + q0, C[1] + p.y + bp1 + q1);
            *(float2*)&sX[(g + 8) * CDIM + c0] =
                make_float2(C[2] + p.z + bp0 + q0, C[3] + p.w + bp1 + q1);
        }
    }
    __syncthreads();

    // ---- Phase 4: LN2 (16 rows, warp per row) -> sAt (bf16) ----
    if (w < 16) {
        const int row = w;
        float4 xv = *(const float4*)&sX[row * CDIM + lane * 4];
        float s1 = xv.x + xv.y + xv.z + xv.w;
        float s2 = xv.x * xv.x + xv.y * xv.y + xv.z * xv.z + xv.w * xv.w;
        s1 = warp_sum(s1);
        s2 = warp_sum(s2);
        float m = s1 * (1.0f / 128.0f);
        float var = s2 * (1.0f / 128.0f) - m * m;
        float rs = rsqrtf(var + LN_EPS);
        float4 gv  = __ldg((const float4*)ln2_g + lane);
        float4 bv2 = __ldg((const float4*)ln2_b + lane);
        *(uint2*)&sAt[row * SAW + lane * 2] = make_uint2(
            bfpack((xv.x - m) * rs * gv.x + bv2.x, (xv.y - m) * rs * gv.y + bv2.y),
            bfpack((xv.z - m) * rs * gv.z + bv2.z, (xv.w - m) * rs * gv.w + bv2.w));
    }
    __syncthreads();

    // ---- Phase 5: f = gelu(ln @ Wf1 + bf1) -> sF ----
    {
        float C[4] = {0.f, 0.f, 0.f, 0.f};
        #pragma unroll
        for (int ks = ksBeg; ks < ksEnd; ks++) {
            const unsigned* pa = sAt + g * SAW + ks * 8 + t;
            unsigned A4[4];
            A4[0] = pa[0];
            A4[1] = pa[8 * SAW];
            A4[2] = pa[4];
            A4[3] = pa[8 * SAW + 4];
            uint2 bb = __ldg(&g_Wf1B[(ks * 16 + nt) * 32 + lane]);
            mma_bf16(C, A4, bb.x, bb.y);
        }
        if (kh == 1)
            *(float4*)&sScr[(nt * 32 + lane) * 4] = make_float4(C[0], C[1], C[2], C[3]);
        __syncthreads();
        if (kh == 0) {
            float4 p = *(const float4*)&sScr[(nt * 32 + lane) * 4];
            const int c0 = nt * 8 + 2 * t;
            const float b10 = __ldg(bf1 + c0), b11 = __ldg(bf1 + c0 + 1);
            float v0 = C[0] + p.x + b10;
            float v1 = C[1] + p.y + b11;
            float v2 = C[2] + p.z + b10;
            float v3 = C[3] + p.w + b11;
            v0 = 0.5f * v0 * (1.0f + erff(v0 * 0.70710678118654752f));
            v1 = 0.5f * v1 * (1.0f + erff(v1 * 0.70710678118654752f));
            v2 = 0.5f * v2 * (1.0f + erff(v2 * 0.70710678118654752f));
            v3 = 0.5f * v3 * (1.0f + erff(v3 * 0.70710678118654752f));
            sF[g * SAW + nt * 4 + t]       = bfpack(v0, v1);
            sF[(g + 8) * SAW + nt * 4 + t] = bfpack(v2, v3);
        }
    }
    __syncthreads();

    // ---- Phase 6: out = x + f @ Wf2 + bf2 ----
    {
        float C[4] = {0.f, 0.f, 0.f, 0.f};
        #pragma unroll
        for (int ks = ksBeg; ks < ksEnd; ks++) {
            const unsigned* pa = sF + g * SAW + ks * 8 + t;
            unsigned A4[4];
            A4[0] = pa[0];
            A4[1] = pa[8 * SAW];
            A4[2] = pa[4];
            A4[3] = pa[8 * SAW + 4];
            uint2 bb = __ldg(&g_Wf2B[(ks * 16 + nt) * 32 + lane]);
            mma_bf16(C, A4, bb.x, bb.y);
        }
        if (kh == 1)
            *(float4*)&sScr[(nt * 32 + lane) * 4] = make_float4(C[0], C[1], C[2], C[3]);
        __syncthreads();
        if (kh == 0) {
            float4 p = *(const float4*)&sScr[(nt * 32 + lane) * 4];
            const int c0 = nt * 8 + 2 * t;
            const float b20 = __ldg(bf2 + c0), b21 = __ldg(bf2 + c0 + 1);
            const float x00 = sX[g * CDIM + c0],       x01 = sX[g * CDIM + c0 + 1];
            const float x10 = sX[(g + 8) * CDIM + c0], x11 = sX[(g + 8) * CDIM + c0 + 1];
            float* ob = out + (size_t)b0 * (NTOK * CDIM);
            *(float2*)&ob[g * CDIM + c0] =
                make_float2(C[0] + p.x + b20 + x00, C[1] + p.y + b21 + x01);
            *(float2*)&ob[(g + 8) * CDIM + c0] =
                make_float2(C[2] + p.z + b20 + x10, C[3] + p.w + b21 + x11);
        }
    }
}

// ---------------- launch ----------------
extern "C" void kernel_launch(void* const* d_in, const int* in_sizes, int n_in,
                              void* d_out, int out_size)
{
    const float* query = (const float*)d_in[0];
    const float* tgt   = (const float*)d_in[1];
    const float* ln1_g = (const float*)d_in[2];
    const float* ln1_b = (const float*)d_in[3];
    const float* ln2_g = (const float*)d_in[4];
    const float* ln2_b = (const float*)d_in[5];
    const float* Wq    = (const float*)d_in[6];
    const float* bq    = (const float*)d_in[7];
    const float* Wk    = (const float*)d_in[8];
    const float* Wv    = (const float*)d_in[10];
    const float* bv    = (const float*)d_in[11];
    const float* Wp    = (const float*)d_in[12];
    const float* bp    = (const float*)d_in[13];
    const float* Wf1   = (const float*)d_in[14];
    const float* bf1   = (const float*)d_in[15];
    const float* Wf2   = (const float*)d_in[16];
    const float* bf2   = (const float*)d_in[17];
    float* out = (float*)d_out;

    const int B = in_sizes[1] / (LTOK * CDIM);

    cudaFuncSetAttribute(mega_kernel, cudaFuncAttributeMaxDynamicSharedMemorySize, SM_MEGA_BYTES);

    precompute1_kernel<<<1, 1024>>>(query, ln1_g, ln1_b, Wq, bq, Wk);
    precompute2_kernel<<<72, 256>>>(Wv, Wp, Wf1, Wf2);
    mega_kernel<<<B / 2, 1024, SM_MEGA_BYTES>>>(
        tgt, query, bv, bp, ln2_g, ln2_b, bf1, bf2, out);
}

// round 6
// speedup vs baseline: 1.3182x; 1.0615x over previous
#include <cuda_runtime.h>
#include <cuda_bf16.h>
#include <math.h>

#define CDIM   128
#define LTOK   54
#define NTOK   8
#define LN_EPS 1e-5f
#define SAW    68        // smem row stride in bf16x2 words (136 bf16)

// ---------------- device globals (precomputed weights) ----------------
__device__ uint2 g_WcB [8 * 24 * 32];   // combined [A_fold | Wv] bf16 B-frags
__device__ uint2 g_WpB [8 * 16 * 32];   // Wp  bf16 B-frags
__device__ uint2 g_Wf1B[8 * 16 * 32];   // Wf1 bf16 B-frags
__device__ uint2 g_Wf2B[8 * 16 * 32];   // Wf2 bf16 B-frags

// ---------------- helpers ----------------
__device__ __forceinline__ unsigned bfpack(float lo, float hi) {
    __nv_bfloat162 h = __floats2bfloat162_rn(lo, hi);
    return *(unsigned*)&h;
}
__device__ __forceinline__ float2 bfunpack(unsigned u) {
    return __bfloat1622float2(*(__nv_bfloat162*)&u);
}

__device__ __forceinline__ void mma_bf16(float* c, const unsigned* a, unsigned b0, unsigned b1) {
    asm volatile(
        "mma.sync.aligned.m16n8k16.row.col.f32.bf16.bf16.f32 "
        "{%0,%1,%2,%3},{%4,%5,%6,%7},{%8,%9},{%0,%1,%2,%3};"
        : "+f"(c[0]), "+f"(c[1]), "+f"(c[2]), "+f"(c[3])
        : "r"(a[0]), "r"(a[1]), "r"(a[2]), "r"(a[3]), "r"(b0), "r"(b1));
}

__device__ __forceinline__ void ldsm_x4(unsigned* r, unsigned saddr) {
    asm volatile(
        "ldmatrix.sync.aligned.m8n8.x4.shared.b16 {%0,%1,%2,%3}, [%4];"
        : "=r"(r[0]), "=r"(r[1]), "=r"(r[2]), "=r"(r[3]) : "r"(saddr));
}

__device__ __forceinline__ float warp_sum(float v) {
    v += __shfl_xor_sync(0xffffffffu, v, 16);
    v += __shfl_xor_sync(0xffffffffu, v, 8);
    v += __shfl_xor_sync(0xffffffffu, v, 4);
    v += __shfl_xor_sync(0xffffffffu, v, 2);
    v += __shfl_xor_sync(0xffffffffu, v, 1);
    return v;
}

// ---------------- precompute: 72 blocks x 256 threads = 18432 pack items ----------------
// Every block redundantly computes LN1(query) -> q (cheap), then packs its slice.
__global__ __launch_bounds__(256, 4) void precompute_kernel(
    const float* __restrict__ query,
    const float* __restrict__ ln1_g, const float* __restrict__ ln1_b,
    const float* __restrict__ Wq, const float* __restrict__ bq,
    const float* __restrict__ Wk,
    const float* __restrict__ Wv,
    const float* __restrict__ Wp,
    const float* __restrict__ Wf1,
    const float* __restrict__ Wf2)
{
    __shared__ float s_qn[NTOK * CDIM];
    __shared__ float s_q[NTOK * CDIM];
    const int tid = threadIdx.x;
    const int warp = tid >> 5, lane = tid & 31;

    if (warp < NTOK) {
        const int r = warp;
        float4 xv = *(const float4*)&query[r * CDIM + lane * 4];
        float s1 = xv.x + xv.y + xv.z + xv.w;
        float s2 = xv.x * xv.x + xv.y * xv.y + xv.z * xv.z + xv.w * xv.w;
        s1 = warp_sum(s1);
        s2 = warp_sum(s2);
        float m = s1 * (1.0f / 128.0f);
        float var = s2 * (1.0f / 128.0f) - m * m;
        float rs = rsqrtf(var + LN_EPS);
        float4 g = *(const float4*)&ln1_g[lane * 4];
        float4 be = *(const float4*)&ln1_b[lane * 4];
        float4 o;
        o.x = (xv.x - m) * rs * g.x + be.x;
        o.y = (xv.y - m) * rs * g.y + be.y;
        o.z = (xv.z - m) * rs * g.z + be.z;
        o.w = (xv.w - m) * rs * g.w + be.w;
        *(float4*)&s_qn[r * CDIM + lane * 4] = o;
    }
    __syncthreads();

    // q = qn @ Wq + bq : 1024 outputs, 4 per thread (coalesced in o)
    #pragma unroll
    for (int j = 0; j < 4; j++) {
        const int idx = tid + j * 256;
        const int t = idx >> 7, o = idx & 127;
        float acc = bq[o];
        #pragma unroll 8
        for (int c = 0; c < CDIM; c++)
            acc += s_qn[t * CDIM + c] * __ldg(Wq + c * CDIM + o);
        s_q[idx] = acc;
    }
    __syncthreads();

    const int gid = blockIdx.x * 256 + tid;
    if (gid < 6144) {
        const int lane2 = gid & 31;
        const int rest = gid >> 5;
        const int nt = rest % 24;
        const int ks = rest / 24;
        const int g = lane2 >> 2, t = lane2 & 3;
        const int c = nt * 8 + g;
        const int k0 = ks * 16 + 2 * t;
        float f0, f1, f2, f3;
        if (c < 64) {
            // A_fold[k][tok*8+h] = 0.25 * sum_j q[tok][h16+j] * Wk[k][h16+j]
            // (bk folds to a per-column constant -> cancels in softmax)
            const int tok = c >> 3, h = c & 7;
            const float* qv = s_q + tok * CDIM + h * 16;
            float a0 = 0.f, a1 = 0.f, a2 = 0.f, a3 = 0.f;
            #pragma unroll
            for (int j = 0; j < 16; j++) {
                const float qj = qv[j];
                a0 += qj * __ldg(Wk + (k0    ) * CDIM + h * 16 + j);
                a1 += qj * __ldg(Wk + (k0 + 1) * CDIM + h * 16 + j);
                a2 += qj * __ldg(Wk + (k0 + 8) * CDIM + h * 16 + j);
                a3 += qj * __ldg(Wk + (k0 + 9) * CDIM + h * 16 + j);
            }
            f0 = 0.25f * a0; f1 = 0.25f * a1; f2 = 0.25f * a2; f3 = 0.25f * a3;
        } else {
            const int cc = c - 64;
            f0 = __ldg(Wv + (k0    ) * CDIM + cc);
            f1 = __ldg(Wv + (k0 + 1) * CDIM + cc);
            f2 = __ldg(Wv + (k0 + 8) * CDIM + cc);
            f3 = __ldg(Wv + (k0 + 9) * CDIM + cc);
        }
        g_WcB[gid] = make_uint2(bfpack(f0, f1), bfpack(f2, f3));
    } else {
        const int r = (gid - 6144) & 4095;
        const int m = (gid - 6144) >> 12;
        const int lane2 = r & 31;
        const int rest = r >> 5;
        const int nt = rest & 15;
        const int ks = rest >> 4;
        const int g = lane2 >> 2, t = lane2 & 3;
        const int c = nt * 8 + g;
        const int k0 = ks * 16 + 2 * t;
        const float* W = (m == 0) ? Wp : (m == 1) ? Wf1 : Wf2;
        uint2 v = make_uint2(
            bfpack(__ldg(W + k0 * CDIM + c), __ldg(W + (k0 + 1) * CDIM + c)),
            bfpack(__ldg(W + (k0 + 8) * CDIM + c), __ldg(W + (k0 + 9) * CDIM + c)));
        if (m == 0)      g_WpB [r] = v;
        else if (m == 1) g_Wf1B[r] = v;
        else             g_Wf2B[r] = v;
    }
}

// ---------------- megakernel: 2 batches per block, 1024 threads ----------------
// smem layout (4B words):
//   sA  [128][SAW] bf16x2 : tgt (2x64 rows), then V            8704 w
//   sB  [6144]     uint2  : GEMM1 B-fragments staged           12288 w
//   sD  [108][68]  fp32   : dots; later k-split scratch        7344 w
//   sAt [16][SAW]  bf16x2 : attn out / LN2 out                 1088 w
//   sF  [16][SAW]  bf16x2 : gelu out                           1088 w
//   sX  [16][128]  fp32   : residual x                         2048 w
#define W_A   (128 * SAW)
#define W_B   (6144 * 2)
#define W_D   (108 * 68)
#define W_AT  (16 * SAW)
#define W_F   (16 * SAW)
#define W_X   (16 * 128)
#define SM_MEGA_BYTES ((W_A + W_B + W_D + W_AT + W_F + W_X) * 4)

__global__ __launch_bounds__(1024, 1) void mega_kernel(
    const float* __restrict__ tgt,
    const float* __restrict__ query,
    const float* __restrict__ bv,
    const float* __restrict__ bp,
    const float* __restrict__ ln2_g, const float* __restrict__ ln2_b,
    const float* __restrict__ bf1, const float* __restrict__ bf2,
    float* __restrict__ out)
{
    extern __shared__ unsigned smw[];
    unsigned* sA  = smw;
    uint2*    sB  = (uint2*)(smw + W_A);
    float*    sD  = (float*)(smw + W_A + W_B);
    unsigned* sAt = smw + W_A + W_B + W_D;
    unsigned* sF  = smw + W_A + W_B + W_D + W_AT;
    float*    sX  = (float*)(smw + W_A + W_B + W_D + W_AT + W_F);
    float*    sScr = sD;

    const int tid = threadIdx.x;
    const int w = tid >> 5, lane = tid & 31;
    const int g = lane >> 2, t = lane & 3;
    const int b0 = blockIdx.x * 2;

    // shared-address bases for ldmatrix
    const unsigned sA_u32  = (unsigned)__cvta_generic_to_shared(sA);
    const unsigned sAt_u32 = (unsigned)__cvta_generic_to_shared(sAt);
    const unsigned sF_u32  = (unsigned)__cvta_generic_to_shared(sF);
    // lane offset within a 16x16 A tile: row = lane&15, col-half = lane>>4
    const unsigned laneoff = (((lane & 15) * SAW + (lane >> 4) * 4) << 2);

    // ---- Phase 0: stage tgt (2 batches, 108 rows) as bf16 + GEMM1 B frags ----
    {
        const float4* gt = (const float4*)(tgt + (size_t)b0 * (LTOK * CDIM));
        for (int i = tid; i < 2 * LTOK * 32; i += 1024) {
            const int row = i >> 5, c4 = i & 31;
            float4 v = __ldg(gt + i);
            const int bb = (row >= LTOK) ? 1 : 0;
            const int r = row - bb * LTOK;
            *(uint2*)&sA[(bb * 64 + r) * SAW + c4 * 2] =
                make_uint2(bfpack(v.x, v.y), bfpack(v.z, v.w));
        }
        const uint4* src = (const uint4*)g_WcB;
        uint4* dst = (uint4*)sB;
        #pragma unroll
        for (int i = 0; i < 3; i++)
            dst[tid + i * 1024] = __ldg(src + tid + i * 1024);
    }
    __syncthreads();

    // ---- Phase 1: GEMM1 [128(2x54),128] @ [128,192] -> dots(64) | V(128) ----
    {
        const int mg = w >> 3;        // m-tile group: tiles {2mg, 2mg+1}
        const int ng = w & 7;         // 3 n-tiles each
        float C[2][3][4];
        #pragma unroll
        for (int m = 0; m < 2; m++)
            #pragma unroll
            for (int n = 0; n < 3; n++)
                #pragma unroll
                for (int q = 0; q < 4; q++) C[m][n][q] = 0.0f;

        #pragma unroll 2
        for (int ks = 0; ks < 8; ks++) {
            uint2 B[3];
            #pragma unroll
            for (int n = 0; n < 3; n++)
                B[n] = sB[(ks * 24 + ng * 3 + n) * 32 + lane];
            #pragma unroll
            for (int m = 0; m < 2; m++) {
                unsigned A4[4];
                ldsm_x4(A4, sA_u32 + (((mg * 2 + m) * 16 * SAW + ks * 8) << 2) + laneoff);
                #pragma unroll
                for (int n = 0; n < 3; n++)
                    mma_bf16(C[m][n], A4, B[n].x, B[n].y);
            }
        }
        __syncthreads();   // all A reads complete before V overwrites sA

        #pragma unroll
        for (int m = 0; m < 2; m++) {
            const int r1 = (mg * 2 + m) * 16 + g;   // global row 0..127
            const int bb = r1 >> 6, rl = r1 & 63;
            #pragma unroll
            for (int n = 0; n < 3; n++) {
                const int nt = ng * 3 + n;
                if (nt < 8) {
                    const int c0 = nt * 8 + 2 * t;
                    float* d0 = sD + (bb * LTOK + rl) * 68 + c0;
                    if (rl < LTOK)     *(float2*)d0            = make_float2(C[m][n][0], C[m][n][1]);
                    if (rl + 8 < LTOK) *(float2*)(d0 + 8 * 68) = make_float2(C[m][n][2], C[m][n][3]);
                } else {
                    const int wrd = (nt - 8) * 4 + t;
                    unsigned* v0 = sA + r1 * SAW + wrd;
                    if (rl < LTOK)     v0[0]       = bfpack(C[m][n][0], C[m][n][1]);
                    if (rl + 8 < LTOK) v0[8 * SAW] = bfpack(C[m][n][2], C[m][n][3]);
                }
            }
        }
    }
    __syncthreads();

    // ---- Phase 2: softmax + AV: 256 tasks (2 batch x 8 tok x 8 head x 2 half) ----
    if (tid < 256) {
        const int bb = tid >> 7;
        const int rest = tid & 127;
        const int th = rest >> 1, half = rest & 1;
        const int tok = th >> 3, h = th & 7;
        const int ridx = (tok < 2) ? tok : (tok - 2);
        const int hb = ridx / 3, wb = ridx % 3;
        const int l0 = hb * 27 + wb * 3;
        int ls[9];
        #pragma unroll
        for (int d = 0; d < 9; d++) ls[d] = l0 + (d / 3) * 9 + (d % 3);

        float dv[9];
        float mx = -1e30f;
        #pragma unroll
        for (int d = 0; d < 9; d++) {
            dv[d] = sD[(bb * LTOK + ls[d]) * 68 + th];
            mx = fmaxf(mx, dv[d]);
        }
        float ssum = 0.0f;
        #pragma unroll
        for (int d = 0; d < 9; d++) {
            dv[d] = __expf(dv[d] - mx);
            ssum += dv[d];
        }
        const float inv = 1.0f / ssum;
        float acc[8];
        #pragma unroll
        for (int j = 0; j < 8; j++) acc[j] = 0.0f;
        #pragma unroll
        for (int d = 0; d < 9; d++) {
            const uint4 vv = *(const uint4*)&sA[(bb * 64 + ls[d]) * SAW + h * 8 + half * 4];
            float2 p;
            p = bfunpack(vv.x); acc[0] += dv[d] * p.x; acc[1] += dv[d] * p.y;
            p = bfunpack(vv.y); acc[2] += dv[d] * p.x; acc[3] += dv[d] * p.y;
            p = bfunpack(vv.z); acc[4] += dv[d] * p.x; acc[5] += dv[d] * p.y;
            p = bfunpack(vv.w); acc[6] += dv[d] * p.x; acc[7] += dv[d] * p.y;
        }
        unsigned* ao = sAt + (bb * 8 + tok) * SAW + h * 8 + half * 4;
        const int cb = h * 16 + half * 8;
        #pragma unroll
        for (int j = 0; j < 4; j++) {
            float v0 = __ldg(bv + cb + 2 * j);
            float v1 = __ldg(bv + cb + 2 * j + 1);
            ao[j] = bfpack(acc[2 * j] * inv + v0, acc[2 * j + 1] * inv + v1);
        }
    }
    __syncthreads();   // sD free: k-split scratch from here

    // ===== tail phases: M=16 x 128, 16 n-tiles x 2 k-halves (all 32 warps) =====
    const int nt = w & 15;
    const int kh = w >> 4;
    const int ksBeg = kh * 4, ksEnd = kh * 4 + 4;

    // ---- Phase 3: proj: x = query + attn @ Wp + bp -> sX ----
    {
        float C[4] = {0.f, 0.f, 0.f, 0.f};
        #pragma unroll
        for (int ks = ksBeg; ks < ksEnd; ks++) {
            unsigned A4[4];
            ldsm_x4(A4, sAt_u32 + ((ks * 8) << 2) + laneoff);
            uint2 bb = __ldg(&g_WpB[(ks * 16 + nt) * 32 + lane]);
            mma_bf16(C, A4, bb.x, bb.y);
        }
        if (kh == 1)
            *(float4*)&sScr[(nt * 32 + lane) * 4] = make_float4(C[0], C[1], C[2], C[3]);
        __syncthreads();
        if (kh == 0) {
            float4 p = *(const float4*)&sScr[(nt * 32 + lane) * 4];
            const int c0 = nt * 8 + 2 * t;
            const float bp0 = __ldg(bp + c0), bp1 = __ldg(bp + c0 + 1);
            const float q0 = __ldg(query + g * CDIM + c0);
            const float q1 = __ldg(query + g * CDIM + c0 + 1);
            *(float2*)&sX[g * CDIM + c0] =
                make_float2(C[0] + p.x + bp0 + q0, C[1] + p.y + bp1 + q1);
            *(float2*)&sX[(g + 8) * CDIM + c0] =
                make_float2(C[2] + p.z + bp0 + q0, C[3] + p.w + bp1 + q1);
        }
    }
    __syncthreads();

    // ---- Phase 4: LN2 (16 rows, warp per row) -> sAt (bf16) ----
    if (w < 16) {
        const int row = w;
        float4 xv = *(const float4*)&sX[row * CDIM + lane * 4];
        float s1 = xv.x + xv.y + xv.z + xv.w;
        float s2 = xv.x * xv.x + xv.y * xv.y + xv.z * xv.z + xv.w * xv.w;
        s1 = warp_sum(s1);
        s2 = warp_sum(s2);
        float m = s1 * (1.0f / 128.0f);
        float var = s2 * (1.0f / 128.0f) - m * m;
        float rs = rsqrtf(var + LN_EPS);
        float4 gv  = __ldg((const float4*)ln2_g + lane);
        float4 bv2 = __ldg((const float4*)ln2_b + lane);
        *(uint2*)&sAt[row * SAW + lane * 2] = make_uint2(
            bfpack((xv.x - m) * rs * gv.x + bv2.x, (xv.y - m) * rs * gv.y + bv2.y),
            bfpack((xv.z - m) * rs * gv.z + bv2.z, (xv.w - m) * rs * gv.w + bv2.w));
    }
    __syncthreads();

    // ---- Phase 5: f = gelu(ln @ Wf1 + bf1) -> sF ----
    {
        float C[4] = {0.f, 0.f, 0.f, 0.f};
        #pragma unroll
        for (int ks = ksBeg; ks < ksEnd; ks++) {
            unsigned A4[4];
            ldsm_x4(A4, sAt_u32 + ((ks * 8) << 2) + laneoff);
            uint2 bb = __ldg(&g_Wf1B[(ks * 16 + nt) * 32 + lane]);
            mma_bf16(C, A4, bb.x, bb.y);
        }
        if (kh == 1)
            *(float4*)&sScr[(nt * 32 + lane) * 4] = make_float4(C[0], C[1], C[2], C[3]);
        __syncthreads();
        if (kh == 0) {
            float4 p = *(const float4*)&sScr[(nt * 32 + lane) * 4];
            const int c0 = nt * 8 + 2 * t;
            const float b10 = __ldg(bf1 + c0), b11 = __ldg(bf1 + c0 + 1);
            float v0 = C[0] + p.x + b10;
            float v1 = C[1] + p.y + b11;
            float v2 = C[2] + p.z + b10;
            float v3 = C[3] + p.w + b11;
            v0 = 0.5f * v0 * (1.0f + erff(v0 * 0.70710678118654752f));
            v1 = 0.5f * v1 * (1.0f + erff(v1 * 0.70710678118654752f));
            v2 = 0.5f * v2 * (1.0f + erff(v2 * 0.70710678118654752f));
            v3 = 0.5f * v3 * (1.0f + erff(v3 * 0.70710678118654752f));
            sF[g * SAW + nt * 4 + t]       = bfpack(v0, v1);
            sF[(g + 8) * SAW + nt * 4 + t] = bfpack(v2, v3);
        }
    }
    __syncthreads();

    // ---- Phase 6: out = x + f @ Wf2 + bf2 ----
    {
        float C[4] = {0.f, 0.f, 0.f, 0.f};
        #pragma unroll
        for (int ks = ksBeg; ks < ksEnd; ks++) {
            unsigned A4[4];
            ldsm_x4(A4, sF_u32 + ((ks * 8) << 2) + laneoff);
            uint2 bb = __ldg(&g_Wf2B[(ks * 16 + nt) * 32 + lane]);
            mma_bf16(C, A4, bb.x, bb.y);
        }
        if (kh == 1)
            *(float4*)&sScr[(nt * 32 + lane) * 4] = make_float4(C[0], C[1], C[2], C[3]);
        __syncthreads();
        if (kh == 0) {
            float4 p = *(const float4*)&sScr[(nt * 32 + lane) * 4];
            const int c0 = nt * 8 + 2 * t;
            const float b20 = __ldg(bf2 + c0), b21 = __ldg(bf2 + c0 + 1);
            const float x00 = sX[g * CDIM + c0],       x01 = sX[g * CDIM + c0 + 1];
            const float x10 = sX[(g + 8) * CDIM + c0], x11 = sX[(g + 8) * CDIM + c0 + 1];
            float* ob = out + (size_t)b0 * (NTOK * CDIM);
            *(float2*)&ob[g * CDIM + c0] =
                make_float2(C[0] + p.x + b20 + x00, C[1] + p.y + b21 + x01);
            *(float2*)&ob[(g + 8) * CDIM + c0] =
                make_float2(C[2] + p.z + b20 + x10, C[3] + p.w + b21 + x11);
        }
    }
}

// ---------------- launch ----------------
extern "C" void kernel_launch(void* const* d_in, const int* in_sizes, int n_in,
                              void* d_out, int out_size)
{
    const float* query = (const float*)d_in[0];
    const float* tgt   = (const float*)d_in[1];
    const float* ln1_g = (const float*)d_in[2];
    const float* ln1_b = (const float*)d_in[3];
    const float* ln2_g = (const float*)d_in[4];
    const float* ln2_b = (const float*)d_in[5];
    const float* Wq    = (const float*)d_in[6];
    const float* bq    = (const float*)d_in[7];
    const float* Wk    = (const float*)d_in[8];
    const float* Wv    = (const float*)d_in[10];
    const float* bv    = (const float*)d_in[11];
    const float* Wp    = (const float*)d_in[12];
    const float* bp    = (const float*)d_in[13];
    const float* Wf1   = (const float*)d_in[14];
    const float* bf1   = (const float*)d_in[15];
    const float* Wf2   = (const float*)d_in[16];
    const float* bf2   = (const float*)d_in[17];
    float* out = (float*)d_out;

    const int B = in_sizes[1] / (LTOK * CDIM);

    cudaFuncSetAttribute(mega_kernel, cudaFuncAttributeMaxDynamicSharedMemorySize, SM_MEGA_BYTES);

    precompute_kernel<<<72, 256>>>(query, ln1_g, ln1_b, Wq, bq, Wk, Wv, Wp, Wf1, Wf2);
    mega_kernel<<<B / 2, 1024, SM_MEGA_BYTES>>>(
        tgt, query, bv, bp, ln2_g, ln2_b, bf1, bf2, out);
}

// round 7
// speedup vs baseline: 1.7352x; 1.3164x over previous
#include <cuda_runtime.h>
#include <cuda_bf16.h>
#include <math.h>

#define CDIM   128
#define LTOK   54
#define NTOK   8
#define LN_EPS 1e-5f
#define SAW    68      // smem row stride in bf16x2 words (17x16B -> ldmatrix conflict-free)
#define SDW    33      // dots row stride in bf16x2 words

// ---------------- device globals (precomputed weights) ----------------
__device__ uint2 g_WcB [8 * 24 * 32];   // combined [A_fold | Wv] bf16 B-frags
__device__ uint2 g_WpB [8 * 16 * 32];   // Wp  bf16 B-frags
__device__ uint2 g_Wf1B[8 * 16 * 32];   // Wf1 bf16 B-frags
__device__ uint2 g_Wf2B[8 * 16 * 32];   // Wf2 bf16 B-frags

// ---------------- helpers ----------------
__device__ __forceinline__ unsigned bfpack(float lo, float hi) {
    __nv_bfloat162 h = __floats2bfloat162_rn(lo, hi);
    return *(unsigned*)&h;
}
__device__ __forceinline__ float2 bfunpack(unsigned u) {
    return __bfloat1622float2(*(__nv_bfloat162*)&u);
}

__device__ __forceinline__ void mma_bf16(float* c, const unsigned* a, unsigned b0, unsigned b1) {
    asm volatile(
        "mma.sync.aligned.m16n8k16.row.col.f32.bf16.bf16.f32 "
        "{%0,%1,%2,%3},{%4,%5,%6,%7},{%8,%9},{%0,%1,%2,%3};"
        : "+f"(c[0]), "+f"(c[1]), "+f"(c[2]), "+f"(c[3])
        : "r"(a[0]), "r"(a[1]), "r"(a[2]), "r"(a[3]), "r"(b0), "r"(b1));
}

__device__ __forceinline__ void ldsm_x4(unsigned* r, unsigned saddr) {
    asm volatile(
        "ldmatrix.sync.aligned.m8n8.x4.shared.b16 {%0,%1,%2,%3}, [%4];"
        : "=r"(r[0]), "=r"(r[1]), "=r"(r[2]), "=r"(r[3]) : "r"(saddr));
}

__device__ __forceinline__ float warp_sum(float v) {
    v += __shfl_xor_sync(0xffffffffu, v, 16);
    v += __shfl_xor_sync(0xffffffffu, v, 8);
    v += __shfl_xor_sync(0xffffffffu, v, 4);
    v += __shfl_xor_sync(0xffffffffu, v, 2);
    v += __shfl_xor_sync(0xffffffffu, v, 1);
    return v;
}

// ---------------- precompute: 72 blocks x 256 threads = 18432 pack items ----------------
__global__ __launch_bounds__(256, 4) void precompute_kernel(
    const float* __restrict__ query,
    const float* __restrict__ ln1_g, const float* __restrict__ ln1_b,
    const float* __restrict__ Wq, const float* __restrict__ bq,
    const float* __restrict__ Wk,
    const float* __restrict__ Wv,
    const float* __restrict__ Wp,
    const float* __restrict__ Wf1,
    const float* __restrict__ Wf2)
{
    __shared__ float s_qn[NTOK * CDIM];
    __shared__ float s_q[NTOK * CDIM];
    const int tid = threadIdx.x;
    const int warp = tid >> 5, lane = tid & 31;

    if (warp < NTOK) {
        const int r = warp;
        float4 xv = *(const float4*)&query[r * CDIM + lane * 4];
        float s1 = xv.x + xv.y + xv.z + xv.w;
        float s2 = xv.x * xv.x + xv.y * xv.y + xv.z * xv.z + xv.w * xv.w;
        s1 = warp_sum(s1);
        s2 = warp_sum(s2);
        float m = s1 * (1.0f / 128.0f);
        float var = s2 * (1.0f / 128.0f) - m * m;
        float rs = rsqrtf(var + LN_EPS);
        float4 g = *(const float4*)&ln1_g[lane * 4];
        float4 be = *(const float4*)&ln1_b[lane * 4];
        float4 o;
        o.x = (xv.x - m) * rs * g.x + be.x;
        o.y = (xv.y - m) * rs * g.y + be.y;
        o.z = (xv.z - m) * rs * g.z + be.z;
        o.w = (xv.w - m) * rs * g.w + be.w;
        *(float4*)&s_qn[r * CDIM + lane * 4] = o;
    }
    __syncthreads();

    #pragma unroll
    for (int j = 0; j < 4; j++) {
        const int idx = tid + j * 256;
        const int t = idx >> 7, o = idx & 127;
        float acc = bq[o];
        #pragma unroll 8
        for (int c = 0; c < CDIM; c++)
            acc += s_qn[t * CDIM + c] * __ldg(Wq + c * CDIM + o);
        s_q[idx] = acc;
    }
    __syncthreads();

    const int gid = blockIdx.x * 256 + tid;
    if (gid < 6144) {
        const int lane2 = gid & 31;
        const int rest = gid >> 5;
        const int nt = rest % 24;
        const int ks = rest / 24;
        const int g = lane2 >> 2, t = lane2 & 3;
        const int c = nt * 8 + g;
        const int k0 = ks * 16 + 2 * t;
        float f0, f1, f2, f3;
        if (c < 64) {
            // A_fold: bk folds to per-column constant -> cancels in softmax
            const int tok = c >> 3, h = c & 7;
            const float* qv = s_q + tok * CDIM + h * 16;
            float a0 = 0.f, a1 = 0.f, a2 = 0.f, a3 = 0.f;
            #pragma unroll
            for (int j = 0; j < 16; j++) {
                const float qj = qv[j];
                a0 += qj * __ldg(Wk + (k0    ) * CDIM + h * 16 + j);
                a1 += qj * __ldg(Wk + (k0 + 1) * CDIM + h * 16 + j);
                a2 += qj * __ldg(Wk + (k0 + 8) * CDIM + h * 16 + j);
                a3 += qj * __ldg(Wk + (k0 + 9) * CDIM + h * 16 + j);
            }
            f0 = 0.25f * a0; f1 = 0.25f * a1; f2 = 0.25f * a2; f3 = 0.25f * a3;
        } else {
            const int cc = c - 64;
            f0 = __ldg(Wv + (k0    ) * CDIM + cc);
            f1 = __ldg(Wv + (k0 + 1) * CDIM + cc);
            f2 = __ldg(Wv + (k0 + 8) * CDIM + cc);
            f3 = __ldg(Wv + (k0 + 9) * CDIM + cc);
        }
        g_WcB[gid] = make_uint2(bfpack(f0, f1), bfpack(f2, f3));
    } else {
        const int r = (gid - 6144) & 4095;
        const int m = (gid - 6144) >> 12;
        const int lane2 = r & 31;
        const int rest = r >> 5;
        const int nt = rest & 15;
        const int ks = rest >> 4;
        const int g = lane2 >> 2, t = lane2 & 3;
        const int c = nt * 8 + g;
        const int k0 = ks * 16 + 2 * t;
        const float* W = (m == 0) ? Wp : (m == 1) ? Wf1 : Wf2;
        uint2 v = make_uint2(
            bfpack(__ldg(W + k0 * CDIM + c), __ldg(W + (k0 + 1) * CDIM + c)),
            bfpack(__ldg(W + (k0 + 8) * CDIM + c), __ldg(W + (k0 + 9) * CDIM + c)));
        if (m == 0)      g_WpB [r] = v;
        else if (m == 1) g_Wf1B[r] = v;
        else             g_Wf2B[r] = v;
    }
}

// ---------------- persistent megakernel: 512 threads, 2 blocks/SM ----------------
// smem layout (4B words):
//   sA  [128][SAW] bf16x2 : tgt (2x64 rows) -> V overwrite     8704 w
//   sB  [6144]     uint2  : GEMM1 B-frags (staged ONCE)        12288 w
//   sDb [108][SDW] bf16x2 : dots (bf16); sF overlays here      3564 w
//   sAt [16][SAW]  bf16x2 : attn out / LN2 out                 1088 w
//   sX  [16][128]  fp32   : residual x                         2048 w
#define W_A   (128 * SAW)
#define W_B   (6144 * 2)
#define W_D   (108 * SDW)
#define W_AT  (16 * SAW)
#define W_X   (16 * 128)
#define OFF_B  (W_A)
#define OFF_D  (W_A + W_B)
#define OFF_AT (W_A + W_B + W_D)
#define OFF_X  (W_A + W_B + W_D + W_AT)
#define SM_MEGA_BYTES ((W_A + W_B + W_D + W_AT + W_X) * 4)

__global__ __launch_bounds__(512, 2) void mega_kernel(
    const float* __restrict__ tgt,
    const float* __restrict__ query,
    const float* __restrict__ bv,
    const float* __restrict__ bp,
    const float* __restrict__ ln2_g, const float* __restrict__ ln2_b,
    const float* __restrict__ bf1, const float* __restrict__ bf2,
    float* __restrict__ out, int npairs)
{
    extern __shared__ unsigned smw[];
    unsigned* sA  = smw;
    uint2*    sB  = (uint2*)(smw + OFF_B);
    unsigned* sDb = smw + OFF_D;
    unsigned* sF  = smw + OFF_D;          // overlays dots (dead when sF live)
    unsigned* sAt = smw + OFF_AT;
    float*    sX  = (float*)(smw + OFF_X);

    const int tid = threadIdx.x;
    const int w = tid >> 5, lane = tid & 31;
    const int g = lane >> 2, t = lane & 3;

    const unsigned sA_u32  = (unsigned)__cvta_generic_to_shared(sA);
    const unsigned sAt_u32 = (unsigned)__cvta_generic_to_shared(sAt);
    const unsigned sF_u32  = (unsigned)__cvta_generic_to_shared(sF);
    const unsigned laneoff = (((lane & 15) * SAW + (lane >> 4) * 4) << 2);

    // ---- stage GEMM1 B-fragments ONCE per block ----
    {
        const uint4* src = (const uint4*)g_WcB;
        uint4* dst = (uint4*)sB;
        #pragma unroll
        for (int i = 0; i < 6; i++)
            dst[tid + i * 512] = __ldg(src + tid + i * 512);
    }

    for (int pair = blockIdx.x; pair < npairs; pair += gridDim.x) {
        const int b0 = pair * 2;
        __syncthreads();   // protect sA / sDb(sF) reuse across iterations

        // ---- Phase 0: stage tgt (2 batches, 108 rows) as bf16 ----
        {
            const float4* gt = (const float4*)(tgt + (size_t)b0 * (LTOK * CDIM));
            #pragma unroll
            for (int i0 = 0; i0 < 7; i0++) {
                const int i = tid + i0 * 512;
                if (i < 2 * LTOK * 32) {
                    const int row = i >> 5, c4 = i & 31;
                    float4 v = __ldg(gt + i);
                    const int bb = (row >= LTOK) ? 1 : 0;
                    const int r = row - bb * LTOK;
                    *(uint2*)&sA[(bb * 64 + r) * SAW + c4 * 2] =
                        make_uint2(bfpack(v.x, v.y), bfpack(v.z, v.w));
                }
            }
        }
        __syncthreads();

        // ---- Phase 1a: GEMM1 dots pass: n-tiles 0..7 ----
        {
            const int a = w & 3;          // m-tile pair {2a, 2a+1}
            const int e = w >> 2;         // n-tile pair {2e, 2e+1}
            float C[2][2][4];
            #pragma unroll
            for (int m = 0; m < 2; m++)
                #pragma unroll
                for (int n = 0; n < 2; n++)
                    #pragma unroll
                    for (int q = 0; q < 4; q++) C[m][n][q] = 0.0f;

            #pragma unroll 2
            for (int ks = 0; ks < 8; ks++) {
                uint2 B[2];
                #pragma unroll
                for (int n = 0; n < 2; n++)
                    B[n] = sB[(ks * 24 + e * 2 + n) * 32 + lane];
                #pragma unroll
                for (int m = 0; m < 2; m++) {
                    unsigned A4[4];
                    ldsm_x4(A4, sA_u32 + (((a * 2 + m) * 16 * SAW + ks * 8) << 2) + laneoff);
                    #pragma unroll
                    for (int n = 0; n < 2; n++)
                        mma_bf16(C[m][n], A4, B[n].x, B[n].y);
                }
            }
            // write dots (bf16 pairs) — sDb disjoint from sA, no barrier needed
            #pragma unroll
            for (int m = 0; m < 2; m++) {
                const int r1 = (a * 2 + m) * 16 + g;
                const int bb = r1 >> 6, rl = r1 & 63;
                #pragma unroll
                for (int n = 0; n < 2; n++) {
                    const int wrd = (e * 2 + n) * 4 + t;
                    unsigned* d0 = sDb + (bb * LTOK + rl) * SDW + wrd;
                    if (rl < LTOK)     d0[0]       = bfpack(C[m][n][0], C[m][n][1]);
                    if (rl + 8 < LTOK) d0[8 * SDW] = bfpack(C[m][n][2], C[m][n][3]);
                }
            }
        }

        // ---- Phase 1b: GEMM1 V pass: n-tiles 8..23 ----
        {
            const int a = w & 3;
            const int e = w >> 2;         // 4 n-tiles each
            float C[2][4][4];
            #pragma unroll
            for (int m = 0; m < 2; m++)
                #pragma unroll
                for (int n = 0; n < 4; n++)
                    #pragma unroll
                    for (int q = 0; q < 4; q++) C[m][n][q] = 0.0f;

            #pragma unroll 2
            for (int ks = 0; ks < 8; ks++) {
                uint2 B[4];
                #pragma unroll
                for (int n = 0; n < 4; n++)
                    B[n] = sB[(ks * 24 + 8 + e * 4 + n) * 32 + lane];
                #pragma unroll
                for (int m = 0; m < 2; m++) {
                    unsigned A4[4];
                    ldsm_x4(A4, sA_u32 + (((a * 2 + m) * 16 * SAW + ks * 8) << 2) + laneoff);
                    #pragma unroll
                    for (int n = 0; n < 4; n++)
                        mma_bf16(C[m][n], A4, B[n].x, B[n].y);
                }
            }
            __syncthreads();   // ALL A reads done before V overwrites sA

            #pragma unroll
            for (int m = 0; m < 2; m++) {
                const int r1 = (a * 2 + m) * 16 + g;
                const int rl = r1 & 63;
                #pragma unroll
                for (int n = 0; n < 4; n++) {
                    const int wrd = (e * 4 + n) * 4 + t;
                    unsigned* v0 = sA + r1 * SAW + wrd;
                    if (rl < LTOK)     v0[0]       = bfpack(C[m][n][0], C[m][n][1]);
                    if (rl + 8 < LTOK) v0[8 * SAW] = bfpack(C[m][n][2], C[m][n][3]);
                }
            }
        }
        __syncthreads();

        // ---- Phase 2: softmax + AV: 512 tasks (2b x 8tok x 8head x 4quarter) ----
        {
            const int bb = tid >> 8;
            const int rest = tid & 255;
            const int th = rest >> 2, qt = rest & 3;
            const int tok = th >> 3, h = th & 7;
            const int ridx = (tok < 2) ? tok : (tok - 2);
            const int hb = ridx / 3, wb = ridx % 3;
            const int l0 = hb * 27 + wb * 3;
            int ls[9];
            #pragma unroll
            for (int d = 0; d < 9; d++) ls[d] = l0 + (d / 3) * 9 + (d % 3);

            const int dw = th >> 1, dh = th & 1;
            float dv[9];
            float mx = -1e30f;
            #pragma unroll
            for (int d = 0; d < 9; d++) {
                float2 p = bfunpack(sDb[(bb * LTOK + ls[d]) * SDW + dw]);
                dv[d] = dh ? p.y : p.x;
                mx = fmaxf(mx, dv[d]);
            }
            float ssum = 0.0f;
            #pragma unroll
            for (int d = 0; d < 9; d++) {
                dv[d] = __expf(dv[d] - mx);
                ssum += dv[d];
            }
            const float inv = 1.0f / ssum;
            float acc[4] = {0.f, 0.f, 0.f, 0.f};
            #pragma unroll
            for (int d = 0; d < 9; d++) {
                const uint2 vv = *(const uint2*)&sA[(bb * 64 + ls[d]) * SAW + h * 8 + qt * 2];
                float2 p;
                p = bfunpack(vv.x); acc[0] += dv[d] * p.x; acc[1] += dv[d] * p.y;
                p = bfunpack(vv.y); acc[2] += dv[d] * p.x; acc[3] += dv[d] * p.y;
            }
            const int cb = h * 16 + qt * 4;
            const float b0v = __ldg(bv + cb),     b1v = __ldg(bv + cb + 1);
            const float b2v = __ldg(bv + cb + 2), b3v = __ldg(bv + cb + 3);
            *(uint2*)&sAt[(bb * 8 + tok) * SAW + h * 8 + qt * 2] = make_uint2(
                bfpack(acc[0] * inv + b0v, acc[1] * inv + b1v),
                bfpack(acc[2] * inv + b2v, acc[3] * inv + b3v));
        }
        __syncthreads();

        // ===== tail: M=16 x 128 GEMMs, warp w owns n-tile w (full k) =====

        // ---- Phase 3: proj: x = query + attn @ Wp + bp -> sX ----
        {
            float C[4] = {0.f, 0.f, 0.f, 0.f};
            #pragma unroll
            for (int ks = 0; ks < 8; ks++) {
                unsigned A4[4];
                ldsm_x4(A4, sAt_u32 + ((ks * 8) << 2) + laneoff);
                uint2 bb2 = __ldg(&g_WpB[(ks * 16 + w) * 32 + lane]);
                mma_bf16(C, A4, bb2.x, bb2.y);
            }
            const int c0 = w * 8 + 2 * t;
            const float bp0 = __ldg(bp + c0), bp1 = __ldg(bp + c0 + 1);
            const float q0 = __ldg(query + g * CDIM + c0);
            const float q1 = __ldg(query + g * CDIM + c0 + 1);
            *(float2*)&sX[g * CDIM + c0]       = make_float2(C[0] + bp0 + q0, C[1] + bp1 + q1);
            *(float2*)&sX[(g + 8) * CDIM + c0] = make_float2(C[2] + bp0 + q0, C[3] + bp1 + q1);
        }
        __syncthreads();

        // ---- Phase 4: LN2 (16 rows, warp per row) -> sAt (bf16) ----
        if (w < 16) {
            const int row = w;
            float4 xv = *(const float4*)&sX[row * CDIM + lane * 4];
            float s1 = xv.x + xv.y + xv.z + xv.w;
            float s2 = xv.x * xv.x + xv.y * xv.y + xv.z * xv.z + xv.w * xv.w;
            s1 = warp_sum(s1);
            s2 = warp_sum(s2);
            float m = s1 * (1.0f / 128.0f);
            float var = s2 * (1.0f / 128.0f) - m * m;
            float rs = rsqrtf(var + LN_EPS);
            float4 gv  = __ldg((const float4*)ln2_g + lane);
            float4 bv2 = __ldg((const float4*)ln2_b + lane);
            *(uint2*)&sAt[row * SAW + lane * 2] = make_uint2(
                bfpack((xv.x - m) * rs * gv.x + bv2.x, (xv.y - m) * rs * gv.y + bv2.y),
                bfpack((xv.z - m) * rs * gv.z + bv2.z, (xv.w - m) * rs * gv.w + bv2.w));
        }
        __syncthreads();

        // ---- Phase 5: f = gelu(ln @ Wf1 + bf1) -> sF (overlays dots) ----
        {
            float C[4] = {0.f, 0.f, 0.f, 0.f};
            #pragma unroll
            for (int ks = 0; ks < 8; ks++) {
                unsigned A4[4];
                ldsm_x4(A4, sAt_u32 + ((ks * 8) << 2) + laneoff);
                uint2 bb2 = __ldg(&g_Wf1B[(ks * 16 + w) * 32 + lane]);
                mma_bf16(C, A4, bb2.x, bb2.y);
            }
            const int c0 = w * 8 + 2 * t;
            const float b10 = __ldg(bf1 + c0), b11 = __ldg(bf1 + c0 + 1);
            float v0 = C[0] + b10, v1 = C[1] + b11;
            float v2 = C[2] + b10, v3 = C[3] + b11;
            v0 = 0.5f * v0 * (1.0f + erff(v0 * 0.70710678118654752f));
            v1 = 0.5f * v1 * (1.0f + erff(v1 * 0.70710678118654752f));
            v2 = 0.5f * v2 * (1.0f + erff(v2 * 0.70710678118654752f));
            v3 = 0.5f * v3 * (1.0f + erff(v3 * 0.70710678118654752f));
            sF[g * SAW + w * 4 + t]       = bfpack(v0, v1);
            sF[(g + 8) * SAW + w * 4 + t] = bfpack(v2, v3);
        }
        __syncthreads();

        // ---- Phase 6: out = x + f @ Wf2 + bf2 ----
        {
            float C[4] = {0.f, 0.f, 0.f, 0.f};
            #pragma unroll
            for (int ks = 0; ks < 8; ks++) {
                unsigned A4[4];
                ldsm_x4(A4, sF_u32 + ((ks * 8) << 2) + laneoff);
                uint2 bb2 = __ldg(&g_Wf2B[(ks * 16 + w) * 32 + lane]);
                mma_bf16(C, A4, bb2.x, bb2.y);
            }
            const int c0 = w * 8 + 2 * t;
            const float b20 = __ldg(bf2 + c0), b21 = __ldg(bf2 + c0 + 1);
            const float x00 = sX[g * CDIM + c0],       x01 = sX[g * CDIM + c0 + 1];
            const float x10 = sX[(g + 8) * CDIM + c0], x11 = sX[(g + 8) * CDIM + c0 + 1];
            float* ob = out + (size_t)b0 * (NTOK * CDIM);
            *(float2*)&ob[g * CDIM + c0] =
                make_float2(C[0] + b20 + x00, C[1] + b21 + x01);
            *(float2*)&ob[(g + 8) * CDIM + c0] =
                make_float2(C[2] + b20 + x10, C[3] + b21 + x11);
        }
    }
}

// ---------------- launch ----------------
extern "C" void kernel_launch(void* const* d_in, const int* in_sizes, int n_in,
                              void* d_out, int out_size)
{
    const float* query = (const float*)d_in[0];
    const float* tgt   = (const float*)d_in[1];
    const float* ln1_g = (const float*)d_in[2];
    const float* ln1_b = (const float*)d_in[3];
    const float* ln2_g = (const float*)d_in[4];
    const float* ln2_b = (const float*)d_in[5];
    const float* Wq    = (const float*)d_in[6];
    const float* bq    = (const float*)d_in[7];
    const float* Wk    = (const float*)d_in[8];
    const float* Wv    = (const float*)d_in[10];
    const float* bv    = (const float*)d_in[11];
    const float* Wp    = (const float*)d_in[12];
    const float* bp    = (const float*)d_in[13];
    const float* Wf1   = (const float*)d_in[14];
    const float* bf1   = (const float*)d_in[15];
    const float* Wf2   = (const float*)d_in[16];
    const float* bf2   = (const float*)d_in[17];
    float* out = (float*)d_out;

    const int B = in_sizes[1] / (LTOK * CDIM);
    const int npairs = B / 2;
    int grid = 296;
    if (grid > npairs) grid = npairs;

    cudaFuncSetAttribute(mega_kernel, cudaFuncAttributeMaxDynamicSharedMemorySize, SM_MEGA_BYTES);

    precompute_kernel<<<72, 256>>>(query, ln1_g, ln1_b, Wq, bq, Wk, Wv, Wp, Wf1, Wf2);
    mega_kernel<<<grid, 512, SM_MEGA_BYTES>>>(
        tgt, query, bv, bp, ln2_g, ln2_b, bf1, bf2, out, npairs);
}